// round 1
// baseline (speedup 1.0000x reference)
#include <cuda_runtime.h>
#include <cuda_bf16.h>

// MoE: out[b,:] = sum_e softmax_e( relu(x Wg1) Wg2 )  *  ( relu(relu(x W1[e]) W2[e]) W3[e] )
// Dims: B=1048576, D_IN=6, E=8, H=32, D_OUT=2. All fp32.
// Strategy (R0 baseline): one thread per token; all weights staged in static smem
// (45 KB); inner 32-wide loops fully unrolled so W2 rows load as LDS.128
// broadcast. Compute-bound on FFMA (~10.7k FMA/token).

#define ED 8
#define DI 6
#define HH 32
#define DO 2

__global__ __launch_bounds__(256)
void moe_kernel(const float* __restrict__ gx,
                const float* __restrict__ gW1, const float* __restrict__ gb1,
                const float* __restrict__ gW2, const float* __restrict__ gb2,
                const float* __restrict__ gW3, const float* __restrict__ gb3,
                const float* __restrict__ gWg1, const float* __restrict__ gbg1,
                const float* __restrict__ gWg2, const float* __restrict__ gbg2,
                float* __restrict__ gout, int B)
{
    // ---- static shared weight cache (44 KB) ----
    __shared__ float sW1[ED * DI * HH];   // 1536
    __shared__ float sb1[ED * HH];        // 256
    __shared__ float sW2[ED * HH * HH];   // 8192
    __shared__ float sb2[ED * HH];        // 256
    __shared__ float sW3[ED * HH * DO];   // 512
    __shared__ float sb3[ED * DO];        // 16
    __shared__ float sWg1[DI * HH];       // 192
    __shared__ float sbg1[HH];            // 32
    __shared__ float sWg2[HH * ED];       // 256
    __shared__ float sbg2[ED];            // 8

    const int tid = threadIdx.x;
    const int nt  = blockDim.x;
    for (int i = tid; i < ED * DI * HH; i += nt) sW1[i] = gW1[i];
    for (int i = tid; i < ED * HH;      i += nt) sb1[i] = gb1[i];
    for (int i = tid; i < ED * HH * HH; i += nt) sW2[i] = gW2[i];
    for (int i = tid; i < ED * HH;      i += nt) sb2[i] = gb2[i];
    for (int i = tid; i < ED * HH * DO; i += nt) sW3[i] = gW3[i];
    for (int i = tid; i < ED * DO;      i += nt) sb3[i] = gb3[i];
    for (int i = tid; i < DI * HH;      i += nt) sWg1[i] = gWg1[i];
    for (int i = tid; i < HH;           i += nt) sbg1[i] = gbg1[i];
    for (int i = tid; i < HH * ED;      i += nt) sWg2[i] = gWg2[i];
    for (int i = tid; i < ED;           i += nt) sbg2[i] = gbg2[i];
    __syncthreads();

    const int b = blockIdx.x * blockDim.x + tid;
    if (b >= B) return;

    // ---- load token ----
    float xv[DI];
    #pragma unroll
    for (int d = 0; d < DI; d++) xv[d] = gx[b * DI + d];

    // ---- gating network ----
    float hg[HH];
    #pragma unroll
    for (int j = 0; j < HH; j++) {
        float a = sbg1[j];
        #pragma unroll
        for (int d = 0; d < DI; d++) a = fmaf(xv[d], sWg1[d * HH + j], a);
        hg[j] = fmaxf(a, 0.0f);
    }
    float lg[ED];
    #pragma unroll
    for (int e = 0; e < ED; e++) {
        float a = sbg2[e];
        #pragma unroll
        for (int j = 0; j < HH; j++) a = fmaf(hg[j], sWg2[j * ED + e], a);
        lg[e] = a;
    }
    // softmax (normalization folded into the final scale)
    float m = lg[0];
    #pragma unroll
    for (int e = 1; e < ED; e++) m = fmaxf(m, lg[e]);
    float ssum = 0.0f;
    #pragma unroll
    for (int e = 0; e < ED; e++) { lg[e] = __expf(lg[e] - m); ssum += lg[e]; }
    const float inv_s = 1.0f / ssum;

    // ---- experts ----
    float o0 = 0.0f, o1 = 0.0f;
    #pragma unroll 1
    for (int e = 0; e < ED; e++) {
        const float* w1 = sW1 + e * DI * HH;
        const float* bb1 = sb1 + e * HH;
        const float* w2 = sW2 + e * HH * HH;
        const float* bb2 = sb2 + e * HH;
        const float* w3 = sW3 + e * HH * DO;

        // layer 1: h1 = relu(x W1 + b1)
        float h1[HH];
        #pragma unroll
        for (int j = 0; j < HH; j++) {
            float a = bb1[j];
            #pragma unroll
            for (int d = 0; d < DI; d++) a = fmaf(xv[d], w1[d * HH + j], a);
            h1[j] = fmaxf(a, 0.0f);
        }

        // layer 2: h2 = relu(h1 W2 + b2)   (the 1024-FMA hot loop)
        float h2[HH];
        #pragma unroll
        for (int j = 0; j < HH; j++) h2[j] = bb2[j];
        #pragma unroll 4
        for (int k = 0; k < HH; k++) {
            const float hk = h1[k];
            const float* w2row = w2 + k * HH;   // 32 consecutive floats -> LDS.128 x8
            #pragma unroll
            for (int j = 0; j < HH; j++) h2[j] = fmaf(hk, w2row[j], h2[j]);
        }
        #pragma unroll
        for (int j = 0; j < HH; j++) h2[j] = fmaxf(h2[j], 0.0f);

        // layer 3: y = h2 W3 + b3  (D_OUT = 2)
        float y0 = sb3[e * DO + 0];
        float y1 = sb3[e * DO + 1];
        #pragma unroll
        for (int k = 0; k < HH; k++) {
            y0 = fmaf(h2[k], w3[k * DO + 0], y0);
            y1 = fmaf(h2[k], w3[k * DO + 1], y1);
        }

        // gate-weighted accumulate (unnormalized softmax weight)
        o0 = fmaf(lg[e], y0, o0);
        o1 = fmaf(lg[e], y1, o1);
    }

    gout[b * DO + 0] = o0 * inv_s;
    gout[b * DO + 1] = o1 * inv_s;
}

extern "C" void kernel_launch(void* const* d_in, const int* in_sizes, int n_in,
                              void* d_out, int out_size)
{
    const float* x   = (const float*)d_in[0];
    const float* W1  = (const float*)d_in[1];
    const float* b1  = (const float*)d_in[2];
    const float* W2  = (const float*)d_in[3];
    const float* b2  = (const float*)d_in[4];
    const float* W3  = (const float*)d_in[5];
    const float* b3  = (const float*)d_in[6];
    const float* Wg1 = (const float*)d_in[7];
    const float* bg1 = (const float*)d_in[8];
    const float* Wg2 = (const float*)d_in[9];
    const float* bg2 = (const float*)d_in[10];
    float* out = (float*)d_out;

    const int B = in_sizes[0] / DI;
    const int threads = 256;
    const int blocks = (B + threads - 1) / threads;
    moe_kernel<<<blocks, threads>>>(x, W1, b1, W2, b2, W3, b3,
                                    Wg1, bg1, Wg2, bg2, out, B);
}

// round 2
// speedup vs baseline: 1.5759x; 1.5759x over previous
#include <cuda_runtime.h>
#include <cuda_bf16.h>

// MoE dense 8-expert, D_IN=6, H=32, D_OUT=2, B=1M, fp32.
// R1: 2 tokens/thread (halves smem bytes per FMA — L1 crossbar is the binding
// pipe at 91.7%) + packed fma.rn.f32x2 over the j-dimension (halves fma-pipe
// issue cost; weight pairs load pre-packed from smem, no packing insts).

#define ED 8
#define DI 6
#define HH 32
#define DO 2

typedef unsigned long long u64;

__device__ __forceinline__ void ffma2_acc(u64& acc, u64 a, u64 b) {
    asm("fma.rn.f32x2 %0, %1, %2, %0;" : "+l"(acc) : "l"(a), "l"(b));
}
__device__ __forceinline__ u64 pack_dup(float v) {
    u64 r;
    asm("mov.b64 %0, {%1, %1};" : "=l"(r) : "r"(__float_as_uint(v)));
    return r;
}
__device__ __forceinline__ float2 unpack2(u64 v) {
    float2 f;
    asm("mov.b64 {%0, %1}, %2;" : "=f"(f.x), "=f"(f.y) : "l"(v));
    return f;
}

__global__ __launch_bounds__(128)
void moe_kernel(const float* __restrict__ gx,
                const float* __restrict__ gW1, const float* __restrict__ gb1,
                const float* __restrict__ gW2, const float* __restrict__ gb2,
                const float* __restrict__ gW3, const float* __restrict__ gb3,
                const float* __restrict__ gWg1, const float* __restrict__ gbg1,
                const float* __restrict__ gWg2, const float* __restrict__ gbg2,
                float* __restrict__ gout, int B)
{
    // ---- static shared weight cache (16B aligned for vector LDS) ----
    __shared__ __align__(16) float sW1[ED * DI * HH];
    __shared__ __align__(16) float sb1[ED * HH];
    __shared__ __align__(16) float sW2[ED * HH * HH];
    __shared__ __align__(16) float sb2[ED * HH];
    __shared__ __align__(16) float sW3[ED * HH * DO];
    __shared__ __align__(16) float sb3[ED * DO];
    __shared__ __align__(16) float sWg1[DI * HH];
    __shared__ __align__(16) float sbg1[HH];
    __shared__ __align__(16) float sWg2[HH * ED];
    __shared__ __align__(16) float sbg2[ED];

    const int tid = threadIdx.x;
    const int nt  = blockDim.x;
    for (int i = tid; i < ED * DI * HH; i += nt) sW1[i] = gW1[i];
    for (int i = tid; i < ED * HH;      i += nt) sb1[i] = gb1[i];
    for (int i = tid; i < ED * HH * HH; i += nt) sW2[i] = gW2[i];
    for (int i = tid; i < ED * HH;      i += nt) sb2[i] = gb2[i];
    for (int i = tid; i < ED * HH * DO; i += nt) sW3[i] = gW3[i];
    for (int i = tid; i < ED * DO;      i += nt) sb3[i] = gb3[i];
    for (int i = tid; i < DI * HH;      i += nt) sWg1[i] = gWg1[i];
    for (int i = tid; i < HH;           i += nt) sbg1[i] = gbg1[i];
    for (int i = tid; i < HH * ED;      i += nt) sWg2[i] = gWg2[i];
    for (int i = tid; i < ED;           i += nt) sbg2[i] = gbg2[i];
    __syncthreads();

    // two tokens per thread: tA = blk*256+tid, tB = tA+128
    const int tA = blockIdx.x * (2 * 128) + tid;
    const int tB = tA + 128;
    if (tA >= B) return;
    const bool hasB = (tB < B);

    float xA[DI], xB[DI];
    #pragma unroll
    for (int d = 0; d < DI; d++) xA[d] = gx[tA * DI + d];
    #pragma unroll
    for (int d = 0; d < DI; d++) xB[d] = hasB ? gx[tB * DI + d] : 0.0f;

    // ---- gating (weights loaded once, used for both tokens) ----
    float hgA[HH], hgB[HH];
    #pragma unroll
    for (int j = 0; j < HH; j++) {
        float bj = sbg1[j];
        float a0 = bj, a1 = bj;
        #pragma unroll
        for (int d = 0; d < DI; d++) {
            float w = sWg1[d * HH + j];
            a0 = fmaf(xA[d], w, a0);
            a1 = fmaf(xB[d], w, a1);
        }
        hgA[j] = fmaxf(a0, 0.0f);
        hgB[j] = fmaxf(a1, 0.0f);
    }
    float lgA[ED], lgB[ED];
    #pragma unroll
    for (int e = 0; e < ED; e++) { lgA[e] = sbg2[e]; lgB[e] = sbg2[e]; }
    #pragma unroll
    for (int j = 0; j < HH; j++) {
        float a = hgA[j], b = hgB[j];
        #pragma unroll
        for (int e = 0; e < ED; e++) {
            float w = sWg2[j * ED + e];
            lgA[e] = fmaf(a, w, lgA[e]);
            lgB[e] = fmaf(b, w, lgB[e]);
        }
    }
    float mA = lgA[0], mB = lgB[0];
    #pragma unroll
    for (int e = 1; e < ED; e++) { mA = fmaxf(mA, lgA[e]); mB = fmaxf(mB, lgB[e]); }
    float sA = 0.0f, sB = 0.0f;
    #pragma unroll
    for (int e = 0; e < ED; e++) {
        lgA[e] = __expf(lgA[e] - mA); sA += lgA[e];
        lgB[e] = __expf(lgB[e] - mB); sB += lgB[e];
    }
    const float invA = 1.0f / sA, invB = 1.0f / sB;

    // ---- experts ----
    float oA0 = 0.0f, oA1 = 0.0f, oB0 = 0.0f, oB1 = 0.0f;
    #pragma unroll 1
    for (int e = 0; e < ED; e++) {
        const float* w1  = sW1 + e * DI * HH;
        const float* bb1 = sb1 + e * HH;
        const float* w2  = sW2 + e * HH * HH;
        const float* bb2 = sb2 + e * HH;
        const float* w3  = sW3 + e * HH * DO;

        // layer 1 (weights shared across both tokens)
        float h1A[HH], h1B[HH];
        #pragma unroll
        for (int j = 0; j < HH; j++) {
            float bj = bb1[j];
            float a0 = bj, a1 = bj;
            #pragma unroll
            for (int d = 0; d < DI; d++) {
                float w = w1[d * HH + j];
                a0 = fmaf(xA[d], w, a0);
                a1 = fmaf(xB[d], w, a1);
            }
            h1A[j] = fmaxf(a0, 0.0f);
            h1B[j] = fmaxf(a1, 0.0f);
        }

        // layer 2: packed f32x2 accumulators over j-pairs, 2 tokens share weights
        u64 accA[HH / 2], accB[HH / 2];
        {
            const u64* b2v = (const u64*)bb2;   // 16B-aligned, pairs pre-packed
            #pragma unroll
            for (int i = 0; i < HH / 2; i++) { accA[i] = b2v[i]; accB[i] = b2v[i]; }
        }
        #pragma unroll 4
        for (int k = 0; k < HH; k++) {
            const u64 hA = pack_dup(h1A[k]);
            const u64 hB = pack_dup(h1B[k]);
            const ulonglong2* wv = (const ulonglong2*)(w2 + k * HH); // 8 x LDS.128
            #pragma unroll
            for (int q = 0; q < HH / 4; q++) {
                ulonglong2 w = wv[q];
                ffma2_acc(accA[2 * q + 0], hA, w.x);
                ffma2_acc(accA[2 * q + 1], hA, w.y);
                ffma2_acc(accB[2 * q + 0], hB, w.x);
                ffma2_acc(accB[2 * q + 1], hB, w.y);
            }
        }

        // relu + layer 3 (D_OUT=2), weights shared across tokens
        float yA0 = sb3[e * DO + 0], yA1 = sb3[e * DO + 1];
        float yB0 = yA0, yB1 = yA1;
        const float2* w3v = (const float2*)w3;  // w3[k*2+0], w3[k*2+1]
        #pragma unroll
        for (int i = 0; i < HH / 2; i++) {
            float2 a = unpack2(accA[i]);
            float2 b = unpack2(accB[i]);
            a.x = fmaxf(a.x, 0.0f); a.y = fmaxf(a.y, 0.0f);
            b.x = fmaxf(b.x, 0.0f); b.y = fmaxf(b.y, 0.0f);
            float2 w30 = w3v[2 * i + 0];
            float2 w31 = w3v[2 * i + 1];
            yA0 = fmaf(a.x, w30.x, yA0); yA1 = fmaf(a.x, w30.y, yA1);
            yA0 = fmaf(a.y, w31.x, yA0); yA1 = fmaf(a.y, w31.y, yA1);
            yB0 = fmaf(b.x, w30.x, yB0); yB1 = fmaf(b.x, w30.y, yB1);
            yB0 = fmaf(b.y, w31.x, yB0); yB1 = fmaf(b.y, w31.y, yB1);
        }

        oA0 = fmaf(lgA[e], yA0, oA0); oA1 = fmaf(lgA[e], yA1, oA1);
        oB0 = fmaf(lgB[e], yB0, oB0); oB1 = fmaf(lgB[e], yB1, oB1);
    }

    ((float2*)gout)[tA] = make_float2(oA0 * invA, oA1 * invA);
    if (hasB) ((float2*)gout)[tB] = make_float2(oB0 * invB, oB1 * invB);
}

extern "C" void kernel_launch(void* const* d_in, const int* in_sizes, int n_in,
                              void* d_out, int out_size)
{
    const float* x   = (const float*)d_in[0];
    const float* W1  = (const float*)d_in[1];
    const float* b1  = (const float*)d_in[2];
    const float* W2  = (const float*)d_in[3];
    const float* b2  = (const float*)d_in[4];
    const float* W3  = (const float*)d_in[5];
    const float* b3  = (const float*)d_in[6];
    const float* Wg1 = (const float*)d_in[7];
    const float* bg1 = (const float*)d_in[8];
    const float* Wg2 = (const float*)d_in[9];
    const float* bg2 = (const float*)d_in[10];
    float* out = (float*)d_out;

    const int B = in_sizes[0] / DI;
    const int tokens_per_block = 2 * 128;
    const int blocks = (B + tokens_per_block - 1) / tokens_per_block;
    moe_kernel<<<blocks, 128>>>(x, W1, b1, W2, b2, W3, b3,
                                Wg1, bg1, Wg2, bg2, out, B);
}

// round 4
// speedup vs baseline: 2.7013x; 1.7141x over previous
#include <cuda_runtime.h>
#include <cuda_bf16.h>
#include <cstdint>

// MoE dense 8-expert: D_IN=6, H=32, D_OUT=2, B=1M, fp32.
// R4: layer-2 via warp-level mma.sync.m16n8k16 bf16 (3-way split for fp32-ish
// precision). Layer1 computed directly in A-fragment layout (no smem round
// trip). B fragments precomputed per-lane in smem. Gate scalar. Per-warp
// tiles of 32 tokens, persistent CTAs.

#define ED 8
#define DI 6
#define HH 32
#define DO 2

typedef unsigned long long u64;
typedef unsigned int u32;

// ---- helpers ----
__device__ __forceinline__ void ffma2_acc(u64& acc, u64 a, u64 b) {
    asm("fma.rn.f32x2 %0, %1, %2, %0;" : "+l"(acc) : "l"(a), "l"(b));
}
__device__ __forceinline__ u64 pack_dup(float v) {
    u64 r; asm("mov.b64 %0, {%1, %1};" : "=l"(r) : "r"(__float_as_uint(v))); return r;
}
__device__ __forceinline__ float2 unpack2(u64 v) {
    float2 f; asm("mov.b64 {%0, %1}, %2;" : "=f"(f.x), "=f"(f.y) : "l"(v)); return f;
}
// pack two f32 -> bf16x2 (element0 = lo arg, element1 = hi arg)
__device__ __forceinline__ u32 bf16x2_of(float lo_e, float hi_e) {
    u32 r; asm("cvt.rn.bf16x2.f32 %0, %1, %2;" : "=r"(r) : "f"(hi_e), "f"(lo_e)); return r;
}
__device__ __forceinline__ float bflo(u32 p) { return __uint_as_float(p << 16); }
__device__ __forceinline__ float bfhi(u32 p) { return __uint_as_float(p & 0xffff0000u); }

__device__ __forceinline__ void mma_bf16(float& d0, float& d1, float& d2, float& d3,
                                         u32 a0, u32 a1, u32 a2, u32 a3,
                                         u32 b0, u32 b1) {
    asm("mma.sync.aligned.m16n8k16.row.col.f32.bf16.bf16.f32 "
        "{%0,%1,%2,%3}, {%4,%5,%6,%7}, {%8,%9}, {%0,%1,%2,%3};"
        : "+f"(d0), "+f"(d1), "+f"(d2), "+f"(d3)
        : "r"(a0), "r"(a1), "r"(a2), "r"(a3), "r"(b0), "r"(b1));
}

// ---- static shared layout (48096 B total) ----
__global__ __launch_bounds__(128)
void moe_mma_kernel(const float* __restrict__ gx,
                    const float* __restrict__ gW1, const float* __restrict__ gb1,
                    const float* __restrict__ gW2, const float* __restrict__ gb2,
                    const float* __restrict__ gW3, const float* __restrict__ gb3,
                    const float* __restrict__ gWg1, const float* __restrict__ gbg1,
                    const float* __restrict__ gWg2, const float* __restrict__ gbg2,
                    float* __restrict__ gout, int B, int NT)
{
    __shared__ __align__(16) float sx[4 * 192];              // per-warp x tiles
    __shared__ __align__(16) char  sBfrag[ED * 8 * 32 * 16]; // [e][chunk0-3 hi,4-7 lo][lane][16B]
    __shared__ __align__(16) float sW1[ED * DI * HH];
    __shared__ __align__(16) float sb1[ED * HH];
    __shared__ __align__(16) float sb2[ED * HH];
    __shared__ __align__(16) float sW3[ED * HH * DO];
    __shared__ __align__(16) float sb3[ED * DO];
    __shared__ __align__(16) float sWg1[DI * HH];
    __shared__ __align__(16) float sbg1[HH];
    __shared__ __align__(16) float sWg2[HH * ED];
    __shared__ __align__(16) float sbg2[ED];

    const int tid  = threadIdx.x;
    const int w    = tid >> 5;
    const int lane = tid & 31;
    const int g    = lane >> 2;   // groupID
    const int q    = lane & 3;    // threadID in group

    // ---- stage small weights ----
    for (int i = tid; i < ED * DI * HH; i += 128) sW1[i]  = gW1[i];
    for (int i = tid; i < ED * HH;      i += 128) sb1[i]  = gb1[i];
    for (int i = tid; i < ED * HH;      i += 128) sb2[i]  = gb2[i];
    for (int i = tid; i < ED * HH * DO; i += 128) sW3[i]  = gW3[i];
    for (int i = tid; i < ED * DO;      i += 128) sb3[i]  = gb3[i];
    for (int i = tid; i < DI * HH;      i += 128) sWg1[i] = gWg1[i];
    for (int i = tid; i < HH;           i += 128) sbg1[i] = gbg1[i];
    for (int i = tid; i < HH * ED;      i += 128) sWg2[i] = gWg2[i];
    for (int i = tid; i < ED;           i += 128) sbg2[i] = gbg2[i];

    // ---- precompute per-lane B fragments (W2 bf16 split) ----
    // chunk c (0..3): kf=c>>1, nfHalf=c&1 -> {b0(nf0),b1(nf0),b0(nf0+1),b1(nf0+1)}; +4 = lo part
    for (int e = w * 2; e < w * 2 + 2; e++) {
        #pragma unroll
        for (int c = 0; c < 4; c++) {
            const int kf = c >> 1, nfh = c & 1;
            u32 hi4[4], lo4[4];
            #pragma unroll
            for (int p = 0; p < 2; p++) {
                const int n  = (nfh * 2 + p) * 8 + g;
                const int k0 = kf * 16 + 2 * q;
                const float w00 = gW2[e * 1024 + (k0    ) * 32 + n];
                const float w01 = gW2[e * 1024 + (k0 + 1) * 32 + n];
                const float w10 = gW2[e * 1024 + (k0 + 8) * 32 + n];
                const float w11 = gW2[e * 1024 + (k0 + 9) * 32 + n];
                const u32 h0 = bf16x2_of(w00, w01);
                const u32 h1 = bf16x2_of(w10, w11);
                hi4[p * 2 + 0] = h0;
                hi4[p * 2 + 1] = h1;
                lo4[p * 2 + 0] = bf16x2_of(w00 - bflo(h0), w01 - bfhi(h0));
                lo4[p * 2 + 1] = bf16x2_of(w10 - bflo(h1), w11 - bfhi(h1));
            }
            *(uint4*)(sBfrag + ((e * 8 + c    ) * 32 + lane) * 16) = make_uint4(hi4[0], hi4[1], hi4[2], hi4[3]);
            *(uint4*)(sBfrag + ((e * 8 + c + 4) * 32 + lane) * 16) = make_uint4(lo4[0], lo4[1], lo4[2], lo4[3]);
        }
    }
    __syncthreads();

    const int lim6 = B * DI;

    // ---- persistent per-warp tile loop (32 tokens per warp) ----
    for (int tile = blockIdx.x; tile < NT; tile += gridDim.x) {
        const int base = tile * 128 + w * 32;   // this warp's first token
        float* sxw = sx + w * 192;
        #pragma unroll
        for (int i = 0; i < 6; i++) {
            const int idx = base * DI + i * 32 + lane;
            sxw[i * 32 + lane] = (idx < lim6) ? gx[idx] : 0.0f;
        }
        __syncwarp();

        // x for this lane's 4 rows (tokens g+8m)
        float xm[4][DI];
        #pragma unroll
        for (int m = 0; m < 4; m++)
            #pragma unroll
            for (int d = 0; d < DI; d++)
                xm[m][d] = sxw[(g + 8 * m) * DI + d];

        // ---- gate for token (g + 8q) ----
        float gg[ED];
        {
            const float* xg = sxw + (g + 8 * q) * DI;
            float xv[DI];
            #pragma unroll
            for (int d = 0; d < DI; d++) xv[d] = xg[d];
            float hg[HH];
            #pragma unroll
            for (int j = 0; j < HH; j++) hg[j] = sbg1[j];
            #pragma unroll
            for (int d = 0; d < DI; d++) {
                const float xd = xv[d];
                #pragma unroll
                for (int j = 0; j < HH; j++) hg[j] = fmaf(xd, sWg1[d * HH + j], hg[j]);
            }
            #pragma unroll
            for (int j = 0; j < HH; j++) hg[j] = fmaxf(hg[j], 0.0f);
            float lg[ED];
            #pragma unroll
            for (int e = 0; e < ED; e++) lg[e] = sbg2[e];
            #pragma unroll
            for (int j = 0; j < HH; j++) {
                const float hj = hg[j];
                #pragma unroll
                for (int e = 0; e < ED; e++) lg[e] = fmaf(hj, sWg2[j * ED + e], lg[e]);
            }
            float mx = lg[0];
            #pragma unroll
            for (int e = 1; e < ED; e++) mx = fmaxf(mx, lg[e]);
            float s = 0.0f;
            #pragma unroll
            for (int e = 0; e < ED; e++) { lg[e] = __expf(lg[e] - mx); s += lg[e]; }
            const float inv = 1.0f / s;
            #pragma unroll
            for (int e = 0; e < ED; e++) gg[e] = lg[e] * inv;
        }

        float2 oP[4];
        #pragma unroll
        for (int m = 0; m < 4; m++) oP[m] = make_float2(0.0f, 0.0f);

        // ---- experts (fully unrolled) ----
        #pragma unroll
        for (int e = 0; e < ED; e++) {
            // layer 1 in fragment layout: acc[m][s] = pair (k=2q+8s, 2q+8s+1) of row g+8m
            u64 acc[4][4];
            #pragma unroll
            for (int s = 0; s < 4; s++) {
                const u64 bp = *(const u64*)&sb1[e * HH + 8 * s + 2 * q];
                acc[0][s] = bp; acc[1][s] = bp; acc[2][s] = bp; acc[3][s] = bp;
            }
            #pragma unroll
            for (int d = 0; d < DI; d++) {
                const u64 xd0 = pack_dup(xm[0][d]);
                const u64 xd1 = pack_dup(xm[1][d]);
                const u64 xd2 = pack_dup(xm[2][d]);
                const u64 xd3 = pack_dup(xm[3][d]);
                #pragma unroll
                for (int s = 0; s < 4; s++) {
                    const u64 wp = *(const u64*)&sW1[e * DI * HH + d * HH + 8 * s + 2 * q];
                    ffma2_acc(acc[0][s], xd0, wp);
                    ffma2_acc(acc[1][s], xd1, wp);
                    ffma2_acc(acc[2][s], xd2, wp);
                    ffma2_acc(acc[3][s], xd3, wp);
                }
            }

            // relu + bf16 split -> A fragments
            u32 ahi[2][2][4], alo[2][2][4];   // [mf][kf][reg]
            #pragma unroll
            for (int m = 0; m < 4; m++) {
                #pragma unroll
                for (int s = 0; s < 4; s++) {
                    const float2 f = unpack2(acc[m][s]);
                    const float h0 = fmaxf(f.x, 0.0f);
                    const float h1 = fmaxf(f.y, 0.0f);
                    const u32 hi = bf16x2_of(h0, h1);
                    const u32 lo = bf16x2_of(h0 - bflo(hi), h1 - bfhi(hi));
                    const int mf = m >> 1, r = m & 1, kf = s >> 1, kr = s & 1;
                    ahi[mf][kf][kr * 2 + r] = hi;
                    alo[mf][kf][kr * 2 + r] = lo;
                }
            }

            // B fragments (precomputed, per-lane, conflict-free LDS.128)
            uint4 cH[4], cL[4];
            #pragma unroll
            for (int c = 0; c < 4; c++) {
                cH[c] = *(const uint4*)(sBfrag + ((e * 8 + c    ) * 32 + lane) * 16);
                cL[c] = *(const uint4*)(sBfrag + ((e * 8 + c + 4) * 32 + lane) * 16);
            }

            // D = A_hi*B_hi + A_lo*B_hi + A_hi*B_lo
            float dd[2][4][4];
            #pragma unroll
            for (int mf = 0; mf < 2; mf++)
                #pragma unroll
                for (int nf = 0; nf < 4; nf++)
                    #pragma unroll
                    for (int r = 0; r < 4; r++) dd[mf][nf][r] = 0.0f;

            #pragma unroll
            for (int kf = 0; kf < 2; kf++) {
                #pragma unroll
                for (int nf = 0; nf < 4; nf++) {
                    const uint4 h4 = cH[kf * 2 + (nf >> 1)];
                    const uint4 l4 = cL[kf * 2 + (nf >> 1)];
                    const u32 b0h = (nf & 1) ? h4.z : h4.x;
                    const u32 b1h = (nf & 1) ? h4.w : h4.y;
                    const u32 b0l = (nf & 1) ? l4.z : l4.x;
                    const u32 b1l = (nf & 1) ? l4.w : l4.y;
                    #pragma unroll
                    for (int mf = 0; mf < 2; mf++) {
                        mma_bf16(dd[mf][nf][0], dd[mf][nf][1], dd[mf][nf][2], dd[mf][nf][3],
                                 ahi[mf][kf][0], ahi[mf][kf][1], ahi[mf][kf][2], ahi[mf][kf][3],
                                 b0h, b1h);
                        mma_bf16(dd[mf][nf][0], dd[mf][nf][1], dd[mf][nf][2], dd[mf][nf][3],
                                 alo[mf][kf][0], alo[mf][kf][1], alo[mf][kf][2], alo[mf][kf][3],
                                 b0h, b1h);
                        mma_bf16(dd[mf][nf][0], dd[mf][nf][1], dd[mf][nf][2], dd[mf][nf][3],
                                 ahi[mf][kf][0], ahi[mf][kf][1], ahi[mf][kf][2], ahi[mf][kf][3],
                                 b0l, b1l);
                    }
                }
            }

            // epilogue: bias + relu + layer3 + gate-weighted accumulate
            float2 b2p[4]; float4 w34[4];
            #pragma unroll
            for (int nf = 0; nf < 4; nf++) {
                b2p[nf] = *(const float2*)&sb2[e * HH + nf * 8 + 2 * q];
                w34[nf] = *(const float4*)&sW3[(e * HH + nf * 8 + 2 * q) * DO];
            }
            const float y0b = sb3[e * DO + 0];
            const float y1b = sb3[e * DO + 1];
            #pragma unroll
            for (int m = 0; m < 4; m++) {
                const int mf = m >> 1, r = m & 1;
                float y0 = y0b, y1 = y1b;
                #pragma unroll
                for (int nf = 0; nf < 4; nf++) {
                    const float ha = fmaxf(dd[mf][nf][r * 2 + 0] + b2p[nf].x, 0.0f);
                    const float hb = fmaxf(dd[mf][nf][r * 2 + 1] + b2p[nf].y, 0.0f);
                    y0 = fmaf(ha, w34[nf].x, y0);
                    y1 = fmaf(ha, w34[nf].y, y1);
                    y0 = fmaf(hb, w34[nf].z, y0);
                    y1 = fmaf(hb, w34[nf].w, y1);
                }
                const float ge = __shfl_sync(0xffffffffu, gg[e], (lane & 28) + m);
                oP[m].x = fmaf(ge, y0, oP[m].x);
                oP[m].y = fmaf(ge, y1, oP[m].y);
            }
        }

        // ---- quad butterfly reduction over col-partials, then write own token ----
        #pragma unroll
        for (int m = 0; m < 4; m++) {
            #pragma unroll
            for (int o = 1; o <= 2; o <<= 1) {
                oP[m].x += __shfl_xor_sync(0xffffffffu, oP[m].x, o);
                oP[m].y += __shfl_xor_sync(0xffffffffu, oP[m].y, o);
            }
        }
        float2 res = oP[0];
        if (q == 1) res = oP[1];
        if (q == 2) res = oP[2];
        if (q == 3) res = oP[3];
        const int t = base + g + 8 * q;
        if (t < B) ((float2*)gout)[t] = res;
    }
}

extern "C" void kernel_launch(void* const* d_in, const int* in_sizes, int n_in,
                              void* d_out, int out_size)
{
    const float* x   = (const float*)d_in[0];
    const float* W1  = (const float*)d_in[1];
    const float* b1  = (const float*)d_in[2];
    const float* W2  = (const float*)d_in[3];
    const float* b2  = (const float*)d_in[4];
    const float* W3  = (const float*)d_in[5];
    const float* b3  = (const float*)d_in[6];
    const float* Wg1 = (const float*)d_in[7];
    const float* bg1 = (const float*)d_in[8];
    const float* Wg2 = (const float*)d_in[9];
    const float* bg2 = (const float*)d_in[10];
    float* out = (float*)d_out;

    const int B  = in_sizes[0] / DI;
    const int NT = (B + 127) / 128;

    int nsm = 148;
    cudaDeviceGetAttribute(&nsm, cudaDevAttrMultiProcessorCount, 0);
    int grid = 2 * nsm;
    if (grid > NT) grid = NT;

    moe_mma_kernel<<<grid, 128>>>(x, W1, b1, W2, b2, W3, b3,
                                  Wg1, bg1, Wg2, bg2, out, B, NT);
}